// round 7
// baseline (speedup 1.0000x reference)
#include <cuda_runtime.h>
#include <cuda_bf16.h>
#include <cstdint>
#include <cstddef>

// ---------------------------------------------------------------------------
// TreeLSTM via mma.sync (HMMA) bf16 GEMM, hi/lo split compensation:
//   C = Ahi*Bhi + Alo*Bhi + Ahi*Blo   (fp32 register accumulation)
// R6: 64x64 warp tiles (BM=128,BN=256) -> 6:1 HMMA:LDSM ratio, tensor-bound.
// ---------------------------------------------------------------------------

#define B_   256
#define LVS  256
#define H_   512
#define X_   300
#define NN   511
#define TH   1536
#define NC   2560
#define KLF  320            // leaf K padded to multiple of 32

// GEMM tiling
#define BM   128
#define BN   256
#define BK   32
#define SPB  80                    // smem row stride bytes (40 bf16), conflict-free
#define OFF_AH 0
#define OFF_AL (128 * SPB)         // 10240
#define OFF_BH (2 * 128 * SPB)     // 20480
#define OFF_BL (OFF_BH + 256 * SPB)
#define STAGE  (OFF_BL + 256 * SPB)   // 61440
#define NST  3
#define SMEM_BYTES (NST * STAGE)      // 184320

// -------------------- static scratch ----------------------------------------
__device__ float         g_c  [(size_t)B_ * NN * H_];
__device__ float         g_buf[(size_t)B_ * LVS * TH];
__device__ __nv_bfloat16 g_hh [(size_t)B_ * NN * H_];
__device__ __nv_bfloat16 g_hl [(size_t)B_ * NN * H_];
__device__ __nv_bfloat16 g_xh [(size_t)B_ * LVS * KLF];
__device__ __nv_bfloat16 g_xl [(size_t)B_ * LVS * KLF];
__device__ __nv_bfloat16 g_wch[(size_t)NC * 1024];
__device__ __nv_bfloat16 g_wcl[(size_t)NC * 1024];
__device__ __nv_bfloat16 g_wlh[(size_t)TH * KLF];
__device__ __nv_bfloat16 g_wll[(size_t)TH * KLF];
__device__ float         g_bc [NC];

// -------------------- PTX helpers -------------------------------------------
__device__ __forceinline__ uint32_t smem_u32(const void* p) {
    uint32_t a;
    asm("{ .reg .u64 t; cvta.to.shared.u64 t, %1; cvt.u32.u64 %0, t; }"
        : "=r"(a) : "l"(p));
    return a;
}
__device__ __forceinline__ void cp16(uint32_t dst, const void* src) {
    asm volatile("cp.async.cg.shared.global [%0], [%1], 16;" :: "r"(dst), "l"(src));
}
__device__ __forceinline__ void cp_commit() {
    asm volatile("cp.async.commit_group;" ::: "memory");
}
template <int N> __device__ __forceinline__ void cp_wait() {
    asm volatile("cp.async.wait_group %0;" :: "n"(N) : "memory");
}
__device__ __forceinline__ void ldmat4(uint32_t* r, uint32_t addr) {
    asm volatile("ldmatrix.sync.aligned.m8n8.x4.shared.b16 {%0,%1,%2,%3}, [%4];"
                 : "=r"(r[0]), "=r"(r[1]), "=r"(r[2]), "=r"(r[3]) : "r"(addr));
}
__device__ __forceinline__ void mma16816(float* c, const uint32_t* a,
                                         uint32_t b0, uint32_t b1) {
    asm volatile(
        "mma.sync.aligned.m16n8k16.row.col.f32.bf16.bf16.f32 "
        "{%0,%1,%2,%3}, {%4,%5,%6,%7}, {%8,%9}, {%0,%1,%2,%3};"
        : "+f"(c[0]), "+f"(c[1]), "+f"(c[2]), "+f"(c[3])
        : "r"(a[0]), "r"(a[1]), "r"(a[2]), "r"(a[3]), "r"(b0), "r"(b1));
}

// -------------------- HMMA GEMM ---------------------------------------------
// C[M, Ntot] = (Ahi+Alo)[M, K] @ (Bhi+Blo)[Ntot, K]^T + bias   (fp32 out)
// tree_lm >= 0: GEMM row r -> contiguous 1024-elem h_cat of node
//               (b = r>>tree_lm, j = r & (m-1)) at level offset off_prev.
__global__ void __launch_bounds__(256, 1) gemm_mma_kernel(
    const __nv_bfloat16* __restrict__ Ah, const __nv_bfloat16* __restrict__ Al,
    const __nv_bfloat16* __restrict__ Bh, const __nv_bfloat16* __restrict__ Bl,
    const float* __restrict__ bias, float* __restrict__ C,
    int Ntot, int Kel, int nk, int tree_lm, int off_prev)
{
    extern __shared__ char smem[];
    const uint32_t sbase = smem_u32(smem);
    const int t = threadIdx.x;
    const int lane = t & 31, wid = t >> 5;
    const int m0 = blockIdx.y * BM, n0 = blockIdx.x * BN;

    // ---------- loader setup ----------
    // A: slots t, t+256  (128 rows x 4 x 16B segs)
    // B: slots t, t+256, t+512, t+768  (256 rows x 4 segs)
    const char* pAh[2];
    const char* pAl[2];
    uint32_t    sA[2];
#pragma unroll
    for (int i = 0; i < 2; i++) {
        const int slot = t + 256 * i;
        const int row = slot >> 2, seg = slot & 3;
        const int gr = m0 + row;
        size_t ab;
        if (tree_lm >= 0) {
            const int msk = (1 << tree_lm) - 1;
            ab = ((size_t)(gr >> tree_lm) * NN + off_prev + 2 * (gr & msk)) * H_;
        } else {
            ab = (size_t)gr * Kel;
        }
        pAh[i] = (const char*)(Ah + ab) + seg * 16;
        pAl[i] = (const char*)(Al + ab) + seg * 16;
        sA[i] = (uint32_t)row * SPB + (uint32_t)seg * 16;
    }
    const char* pBh[4];
    const char* pBl[4];
    uint32_t    sB[4];
#pragma unroll
    for (int i = 0; i < 4; i++) {
        const int slot = t + 256 * i;
        const int row = slot >> 2, seg = slot & 3;
        pBh[i] = (const char*)(Bh + (size_t)(n0 + row) * Kel) + seg * 16;
        pBl[i] = (const char*)(Bl + (size_t)(n0 + row) * Kel) + seg * 16;
        sB[i] = (uint32_t)row * SPB + (uint32_t)seg * 16;
    }

#define LOADS(kk, st) do {                                                    \
        const uint32_t sb_ = sbase + (uint32_t)(st) * STAGE;                  \
        const size_t gb_ = (size_t)(kk) * 64;                                 \
        _Pragma("unroll")                                                     \
        for (int i = 0; i < 2; i++) {                                         \
            cp16(sb_ + OFF_AH + sA[i], pAh[i] + gb_);                         \
            cp16(sb_ + OFF_AL + sA[i], pAl[i] + gb_);                         \
        }                                                                     \
        _Pragma("unroll")                                                     \
        for (int i = 0; i < 4; i++) {                                         \
            cp16(sb_ + OFF_BH + sB[i], pBh[i] + gb_);                         \
            cp16(sb_ + OFF_BL + sB[i], pBl[i] + gb_);                         \
        }                                                                     \
        cp_commit();                                                          \
    } while (0)

    // ---------- compute setup: 2x4 warp grid, 64x64 warp tiles ----------
    const int warp_m = (wid & 1) * 64, warp_n = (wid >> 1) * 64;
    const uint32_t aoff = (uint32_t)(warp_m + (lane & 15)) * SPB
                        + ((uint32_t)(lane >> 4) << 4);
    const uint32_t boff = (uint32_t)(warp_n + (lane & 15)) * SPB
                        + ((uint32_t)(lane >> 4) << 4);

    float acc[4][8][4];
#pragma unroll
    for (int mi = 0; mi < 4; mi++)
#pragma unroll
        for (int nj = 0; nj < 8; nj++)
#pragma unroll
            for (int q = 0; q < 4; q++) acc[mi][nj][q] = 0.0f;

    LOADS(0, 0);
    LOADS(1, 1);

    int st = 0;
    for (int k = 0; k < nk; k++) {
        __syncthreads();                 // all warps done with stage (k+2)%3
        if (k + 2 < nk) LOADS(k + 2, (k + 2) % NST);
        else            cp_commit();     // keep group accounting aligned
        cp_wait<2>();                    // drain chunk k's group
        __syncthreads();                 // chunk k visible to all warps

        const uint32_t sb = sbase + (uint32_t)st * STAGE;
#pragma unroll
        for (int ks = 0; ks < 2; ks++) {
            uint32_t ah[4][4], al[4][4];
#pragma unroll
            for (int mi = 0; mi < 4; mi++) {
                const uint32_t o = aoff + (uint32_t)mi * (16 * SPB) + ks * 32;
                ldmat4(ah[mi], sb + OFF_AH + o);
                ldmat4(al[mi], sb + OFF_AL + o);
            }
#pragma unroll
            for (int g = 0; g < 4; g++) {
                uint32_t bh[4], bl[4];
                const uint32_t o = boff + (uint32_t)g * (16 * SPB) + ks * 32;
                ldmat4(bh, sb + OFF_BH + o);
                ldmat4(bl, sb + OFF_BL + o);
                // product-major: same-acc reuse distance = 8 HMMAs
#pragma unroll
                for (int mi = 0; mi < 4; mi++) {
                    mma16816(acc[mi][2 * g],     ah[mi], bh[0], bh[2]);
                    mma16816(acc[mi][2 * g + 1], ah[mi], bh[1], bh[3]);
                }
#pragma unroll
                for (int mi = 0; mi < 4; mi++) {
                    mma16816(acc[mi][2 * g],     al[mi], bh[0], bh[2]);
                    mma16816(acc[mi][2 * g + 1], al[mi], bh[1], bh[3]);
                }
#pragma unroll
                for (int mi = 0; mi < 4; mi++) {
                    mma16816(acc[mi][2 * g],     ah[mi], bl[0], bl[2]);
                    mma16816(acc[mi][2 * g + 1], ah[mi], bl[1], bl[3]);
                }
            }
        }
        st = (st + 1 == NST) ? 0 : st + 1;
    }

    // ---------- epilogue ----------
    const int er = lane >> 2, ec = (lane & 3) * 2;
#pragma unroll
    for (int mi = 0; mi < 4; mi++) {
        const int rbase = m0 + warp_m + mi * 16 + er;
#pragma unroll
        for (int nj = 0; nj < 8; nj++) {
            const int col = n0 + warp_n + nj * 8 + ec;
            const float b0 = bias[col], b1 = bias[col + 1];
            float2 v;
            v.x = acc[mi][nj][0] + b0;
            v.y = acc[mi][nj][1] + b1;
            *(float2*)&C[(size_t)rbase * Ntot + col] = v;
            v.x = acc[mi][nj][2] + b0;
            v.y = acc[mi][nj][3] + b1;
            *(float2*)&C[(size_t)(rbase + 8) * Ntot + col] = v;
        }
    }
#undef LOADS
}

// -------------------- cell / epilogue kernels -------------------------------
__device__ __forceinline__ float sigf(float x) { return 1.0f / (1.0f + expf(-x)); }

__device__ __forceinline__ void store_h(size_t ob, float hn) {
    const __nv_bfloat16 hi = __float2bfloat16(hn);
    g_hh[ob] = hi;
    g_hl[ob] = __float2bfloat16(hn - __bfloat162float(hi));
}

__global__ void cell_leaf_kernel(const float* __restrict__ buf)
{
    const size_t idx = (size_t)blockIdx.x * blockDim.x + threadIdx.x;
    if (idx >= (size_t)B_ * LVS * H_) return;
    const int n = (int)(idx & (H_ - 1));
    const size_t r = idx >> 9;
    const float* row = buf + r * TH;
    const float i_ = row[n], o_ = row[n + 512], u_ = row[n + 1024];
    const float cn = sigf(i_) * tanhf(u_);
    const float hn = sigf(o_) * tanhf(cn);
    const int b = (int)(r >> 8), leaf = (int)(r & 255);
    const size_t ob = ((size_t)b * NN + leaf) * H_ + n;
    g_c[ob] = cn;
    store_h(ob, hn);
}

__global__ void cell_level_kernel(const float* __restrict__ buf,
                                  int lm, int off, int off_prev, int total)
{
    const int idx = blockIdx.x * blockDim.x + threadIdx.x;
    if (idx >= total) return;
    const int n = idx & (H_ - 1);
    const int r = idx >> 9;
    const int b = r >> lm;
    const int j = r & ((1 << lm) - 1);
    const float* row = buf + (size_t)r * NC;
    const float i_ = row[n], o_ = row[n + 512], u_ = row[n + 1024];
    const float f0 = row[1536 + n], f1 = row[2048 + n];
    const size_t cb = ((size_t)b * NN + off_prev + 2 * j) * H_ + n;
    const float cf = sigf(f0) * g_c[cb] + sigf(f1) * g_c[cb + H_];
    const float cn = sigf(i_) * tanhf(u_) + cf;
    const float hn = sigf(o_) * tanhf(cn);
    const size_t ob = ((size_t)b * NN + off + j) * H_ + n;
    g_c[ob] = cn;
    store_h(ob, hn);
}

__global__ void classify_kernel(const float* __restrict__ lw,
                                const float* __restrict__ lb,
                                float* __restrict__ out)
{
    const int node = blockIdx.x * blockDim.x + threadIdx.x;
    if (node >= B_ * NN) return;
    const __nv_bfloat162* hh = (const __nv_bfloat162*)(g_hh + (size_t)node * H_);
    const __nv_bfloat162* hl = (const __nv_bfloat162*)(g_hl + (size_t)node * H_);
    float acc[5] = {0.f, 0.f, 0.f, 0.f, 0.f};
#pragma unroll 4
    for (int k2 = 0; k2 < 256; k2++) {
        const float2 a = __bfloat1622float2(hh[k2]);
        const float2 b = __bfloat1622float2(hl[k2]);
        const float h0 = a.x + b.x, h1 = a.y + b.y;
#pragma unroll
        for (int c = 0; c < 5; c++)
            acc[c] += h0 * lw[c * H_ + 2 * k2] + h1 * lw[c * H_ + 2 * k2 + 1];
    }
#pragma unroll
    for (int c = 0; c < 5; c++)
        out[(size_t)node * 5 + c] = acc[c] + lb[c];
}

// -------------------- packing / gather --------------------------------------
__device__ __forceinline__ void split_bf16(float v, __nv_bfloat16* hi,
                                           __nv_bfloat16* lo, size_t i) {
    const __nv_bfloat16 h = __float2bfloat16(v);
    hi[i] = h;
    lo[i] = __float2bfloat16(v - __bfloat162float(h));
}

__global__ void pack_wcat_kernel(const float* __restrict__ Uiou,
                                 const float* __restrict__ Uf)
{
    const int idx = blockIdx.x * blockDim.x + threadIdx.x;
    if (idx >= NC * 1024) return;
    const int n = idx >> 10, k = idx & 1023;
    const float v = (n < TH) ? Uiou[(size_t)n * 1024 + k]
                             : Uf[(size_t)(n - TH) * 1024 + k];
    split_bf16(v, g_wch, g_wcl, idx);
}

__global__ void pack_wleaf_kernel(const float* __restrict__ W)
{
    const int idx = blockIdx.x * blockDim.x + threadIdx.x;
    if (idx >= TH * KLF) return;
    const int n = idx / KLF, k = idx - n * KLF;
    const float v = (k < X_) ? W[(size_t)n * X_ + k] : 0.0f;
    split_bf16(v, g_wlh, g_wll, idx);
}

__global__ void pack_bias_kernel(const float* __restrict__ bi,
                                 const float* __restrict__ bf)
{
    const int n = blockIdx.x * blockDim.x + threadIdx.x;
    if (n < NC) g_bc[n] = (n < TH) ? bi[n] : bf[n - TH];
}

__global__ void gather_x_kernel(const int* __restrict__ wid,
                                const float* __restrict__ emb)
{
    const int r = blockIdx.x;
    const int c = threadIdx.x;
    if (c >= KLF) return;
    const float v = (c < X_) ? emb[(size_t)wid[r] * X_ + c] : 0.0f;
    split_bf16(v, g_xh, g_xl, (size_t)r * KLF + c);
}

// -------------------- launch ------------------------------------------------
extern "C" void kernel_launch(void* const* d_in, const int* in_sizes, int n_in,
                              void* d_out, int out_size)
{
    const int*   wordid  = (const int*)  d_in[0];
    const float* emb     = (const float*)d_in[1];
    const float* W_iou_w = (const float*)d_in[2];
    const float* W_iou_b = (const float*)d_in[3];
    const float* U_iou_w = (const float*)d_in[4];
    const float* U_iou_b = (const float*)d_in[5];
    const float* U_f_w   = (const float*)d_in[6];
    const float* U_f_b   = (const float*)d_in[7];
    const float* lin_w   = (const float*)d_in[8];
    const float* lin_b   = (const float*)d_in[9];
    float* out = (float*)d_out;
    (void)in_sizes; (void)n_in; (void)out_size;

    float *pbuf, *pbc;
    __nv_bfloat16 *phh, *phl, *pxh, *pxl, *pwch, *pwcl, *pwlh, *pwll;
    cudaGetSymbolAddress((void**)&pbuf, g_buf);
    cudaGetSymbolAddress((void**)&pbc,  g_bc);
    cudaGetSymbolAddress((void**)&phh,  g_hh);
    cudaGetSymbolAddress((void**)&phl,  g_hl);
    cudaGetSymbolAddress((void**)&pxh,  g_xh);
    cudaGetSymbolAddress((void**)&pxl,  g_xl);
    cudaGetSymbolAddress((void**)&pwch, g_wch);
    cudaGetSymbolAddress((void**)&pwcl, g_wcl);
    cudaGetSymbolAddress((void**)&pwlh, g_wlh);
    cudaGetSymbolAddress((void**)&pwll, g_wll);

    cudaFuncSetAttribute(gemm_mma_kernel,
                         cudaFuncAttributeMaxDynamicSharedMemorySize, SMEM_BYTES);

    // ---- prep ----
    pack_wcat_kernel <<<(NC * 1024 + 255) / 256, 256>>>(U_iou_w, U_f_w);
    pack_wleaf_kernel<<<(TH * KLF + 255) / 256, 256>>>(W_iou_w);
    pack_bias_kernel <<<(NC + 255) / 256, 256>>>(U_iou_b, U_f_b);
    gather_x_kernel  <<<B_ * LVS, KLF>>>(wordid, emb);

    // ---- leaves ----
    {
        dim3 g(TH / BN, (B_ * LVS) / BM);
        gemm_mma_kernel<<<g, 256, SMEM_BYTES>>>(pxh, pxl, pwlh, pwll, W_iou_b,
                                                pbuf, TH, KLF, KLF / BK, -1, 0);
        cell_leaf_kernel<<<(B_ * LVS * H_) / 256, 256>>>(pbuf);
    }

    // ---- internal levels ----
    static const int offs[10] = {0, 256, 384, 448, 480, 496, 504, 508, 510, 511};
    for (int l = 1; l <= 8; l++) {
        const int m = LVS >> l;
        const int M = B_ * m;
        const int lm = 8 - l;
        dim3 g(NC / BN, M / BM);
        gemm_mma_kernel<<<g, 256, SMEM_BYTES>>>(phh, phl, pwch, pwcl, pbc,
                                                pbuf, NC, 1024, 1024 / BK,
                                                lm, offs[l - 1]);
        const int total = M * H_;
        cell_level_kernel<<<(total + 255) / 256, 256>>>(pbuf, lm, offs[l],
                                                        offs[l - 1], total);
    }

    // ---- classifier ----
    classify_kernel<<<(B_ * NN + 127) / 128, 128>>>(lin_w, lin_b, out);
}

// round 8
// speedup vs baseline: 1.0984x; 1.0984x over previous
#include <cuda_runtime.h>
#include <cuda_bf16.h>
#include <cstdint>
#include <cstddef>

// ---------------------------------------------------------------------------
// TreeLSTM via mma.sync (HMMA) bf16 GEMM, hi/lo split compensation:
//   C = Ahi*Bhi + Alo*Bhi + Ahi*Blo   (fp32 register accumulation)
// R8: R4 tiling (BM=128,BN=128, 32x64 warp tiles) + 2-stage pipeline so two
//     CTAs co-reside per SM (occupancy 2) and hide barrier/memory bubbles.
// ---------------------------------------------------------------------------

#define B_   256
#define LVS  256
#define H_   512
#define X_   300
#define NN   511
#define TH   1536
#define NC   2560
#define KLF  320            // leaf K padded to multiple of 32

// GEMM tiling
#define BM   128
#define BN   128
#define BK   32
#define SPB  80                    // smem row stride bytes (40 bf16): 16B-aligned,
                                   // ldmatrix conflict-free (banks 20r mod 32)
#define TILEB (128 * SPB)          // 10240 B
#define OFF_AH 0
#define OFF_AL TILEB
#define OFF_BH (2 * TILEB)
#define OFF_BL (3 * TILEB)
#define STAGE  (4 * TILEB)         // 40960
#define NST  2
#define SMEM_BYTES (NST * STAGE)   // 81920 -> 2 CTAs/SM

// -------------------- static scratch ----------------------------------------
__device__ float         g_c  [(size_t)B_ * NN * H_];
__device__ float         g_buf[(size_t)B_ * LVS * TH];
__device__ __nv_bfloat16 g_hh [(size_t)B_ * NN * H_];
__device__ __nv_bfloat16 g_hl [(size_t)B_ * NN * H_];
__device__ __nv_bfloat16 g_xh [(size_t)B_ * LVS * KLF];
__device__ __nv_bfloat16 g_xl [(size_t)B_ * LVS * KLF];
__device__ __nv_bfloat16 g_wch[(size_t)NC * 1024];
__device__ __nv_bfloat16 g_wcl[(size_t)NC * 1024];
__device__ __nv_bfloat16 g_wlh[(size_t)TH * KLF];
__device__ __nv_bfloat16 g_wll[(size_t)TH * KLF];
__device__ float         g_bc [NC];

// -------------------- PTX helpers -------------------------------------------
__device__ __forceinline__ uint32_t smem_u32(const void* p) {
    uint32_t a;
    asm("{ .reg .u64 t; cvta.to.shared.u64 t, %1; cvt.u32.u64 %0, t; }"
        : "=r"(a) : "l"(p));
    return a;
}
__device__ __forceinline__ void cp16(uint32_t dst, const void* src) {
    asm volatile("cp.async.cg.shared.global [%0], [%1], 16;" :: "r"(dst), "l"(src));
}
__device__ __forceinline__ void cp_commit() {
    asm volatile("cp.async.commit_group;" ::: "memory");
}
template <int N> __device__ __forceinline__ void cp_wait() {
    asm volatile("cp.async.wait_group %0;" :: "n"(N) : "memory");
}
__device__ __forceinline__ void ldmat4(uint32_t* r, uint32_t addr) {
    asm volatile("ldmatrix.sync.aligned.m8n8.x4.shared.b16 {%0,%1,%2,%3}, [%4];"
                 : "=r"(r[0]), "=r"(r[1]), "=r"(r[2]), "=r"(r[3]) : "r"(addr));
}
__device__ __forceinline__ void mma16816(float* c, const uint32_t* a,
                                         uint32_t b0, uint32_t b1) {
    asm volatile(
        "mma.sync.aligned.m16n8k16.row.col.f32.bf16.bf16.f32 "
        "{%0,%1,%2,%3}, {%4,%5,%6,%7}, {%8,%9}, {%0,%1,%2,%3};"
        : "+f"(c[0]), "+f"(c[1]), "+f"(c[2]), "+f"(c[3])
        : "r"(a[0]), "r"(a[1]), "r"(a[2]), "r"(a[3]), "r"(b0), "r"(b1));
}

// -------------------- HMMA GEMM ---------------------------------------------
// C[M, Ntot] = (Ahi+Alo)[M, K] @ (Bhi+Blo)[Ntot, K]^T + bias   (fp32 out)
// tree_lm >= 0: GEMM row r -> contiguous 1024-elem h_cat of node
//               (b = r>>tree_lm, j = r & (m-1)) at level offset off_prev.
__global__ void __launch_bounds__(256, 2) gemm_mma_kernel(
    const __nv_bfloat16* __restrict__ Ah, const __nv_bfloat16* __restrict__ Al,
    const __nv_bfloat16* __restrict__ Bh, const __nv_bfloat16* __restrict__ Bl,
    const float* __restrict__ bias, float* __restrict__ C,
    int Ntot, int Kel, int nk, int tree_lm, int off_prev)
{
    extern __shared__ char smem[];
    const uint32_t sbase = smem_u32(smem);
    const int t = threadIdx.x;
    const int lane = t & 31, wid = t >> 5;
    const int m0 = blockIdx.y * BM, n0 = blockIdx.x * BN;

    // ---------- loader setup: thread -> rows (t>>2) and (t>>2)+64, seg t&3 --
    const int lr0 = t >> 2;
    const int lj  = t & 3;
    const uint32_t s0 = (uint32_t)lr0 * SPB + (uint32_t)lj * 16;
    const uint32_t s1 = s0 + 64 * SPB;
    size_t a0b, a1b;
    {
        const int gr0 = m0 + lr0, gr1 = gr0 + 64;
        if (tree_lm >= 0) {
            const int msk = (1 << tree_lm) - 1;
            a0b = ((size_t)(gr0 >> tree_lm) * NN + off_prev + 2 * (gr0 & msk)) * H_;
            a1b = ((size_t)(gr1 >> tree_lm) * NN + off_prev + 2 * (gr1 & msk)) * H_;
        } else {
            a0b = (size_t)gr0 * Kel;
            a1b = (size_t)gr1 * Kel;
        }
    }
    const char* pAh0 = (const char*)(Ah + a0b);
    const char* pAh1 = (const char*)(Ah + a1b);
    const char* pAl0 = (const char*)(Al + a0b);
    const char* pAl1 = (const char*)(Al + a1b);
    const char* pBh0 = (const char*)(Bh + (size_t)(n0 + lr0) * Kel);
    const char* pBh1 = (const char*)(Bh + (size_t)(n0 + lr0 + 64) * Kel);
    const char* pBl0 = (const char*)(Bl + (size_t)(n0 + lr0) * Kel);
    const char* pBl1 = (const char*)(Bl + (size_t)(n0 + lr0 + 64) * Kel);
    const uint32_t jb = (uint32_t)lj * 16;

#define LOADS(kk, st) do {                                                    \
        const uint32_t sb_ = sbase + (uint32_t)(st) * STAGE;                  \
        const size_t gb_ = (size_t)(kk) * 64 + jb;                            \
        cp16(sb_ + OFF_AH + s0, pAh0 + gb_);                                  \
        cp16(sb_ + OFF_AH + s1, pAh1 + gb_);                                  \
        cp16(sb_ + OFF_AL + s0, pAl0 + gb_);                                  \
        cp16(sb_ + OFF_AL + s1, pAl1 + gb_);                                  \
        cp16(sb_ + OFF_BH + s0, pBh0 + gb_);                                  \
        cp16(sb_ + OFF_BH + s1, pBh1 + gb_);                                  \
        cp16(sb_ + OFF_BL + s0, pBl0 + gb_);                                  \
        cp16(sb_ + OFF_BL + s1, pBl1 + gb_);                                  \
        cp_commit();                                                          \
    } while (0)

    // ---------- compute setup: 4x2 warp grid, 32x64 warp tile ----------
    const int warp_m = (wid & 3) * 32, warp_n = (wid >> 2) * 64;
    const uint32_t aoff = (uint32_t)(warp_m + (lane & 15)) * SPB
                        + ((uint32_t)(lane >> 4) << 4);
    const uint32_t boff = (uint32_t)(warp_n + (lane & 15)) * SPB
                        + ((uint32_t)(lane >> 4) << 4);

    float acc[2][8][4];
#pragma unroll
    for (int mi = 0; mi < 2; mi++)
#pragma unroll
        for (int nj = 0; nj < 8; nj++)
#pragma unroll
            for (int q = 0; q < 4; q++) acc[mi][nj][q] = 0.0f;

    LOADS(0, 0);
    LOADS(1, 1);

    for (int k = 0; k < nk; k++) {
        if (k + 1 < nk) cp_wait<1>();    // chunk k's group complete
        else            cp_wait<0>();
        __syncthreads();                 // all threads' chunk-k data visible

        const uint32_t sb = sbase + (uint32_t)(k & 1) * STAGE;
#pragma unroll
        for (int ks = 0; ks < 2; ks++) {
            uint32_t ah[2][4], al[2][4];
#pragma unroll
            for (int mi = 0; mi < 2; mi++) {
                const uint32_t o = aoff + (uint32_t)mi * (16 * SPB) + ks * 32;
                ldmat4(ah[mi], sb + OFF_AH + o);
                ldmat4(al[mi], sb + OFF_AL + o);
            }
#pragma unroll
            for (int g = 0; g < 4; g++) {
                uint32_t bh[4], bl[4];
                const uint32_t o = boff + (uint32_t)g * (16 * SPB) + ks * 32;
                ldmat4(bh, sb + OFF_BH + o);
                ldmat4(bl, sb + OFF_BL + o);
                // product-major within g: same-acc reuse distance = 4
#pragma unroll
                for (int mi = 0; mi < 2; mi++) {
                    mma16816(acc[mi][2 * g],     ah[mi], bh[0], bh[2]);
                    mma16816(acc[mi][2 * g + 1], ah[mi], bh[1], bh[3]);
                }
#pragma unroll
                for (int mi = 0; mi < 2; mi++) {
                    mma16816(acc[mi][2 * g],     al[mi], bh[0], bh[2]);
                    mma16816(acc[mi][2 * g + 1], al[mi], bh[1], bh[3]);
                }
#pragma unroll
                for (int mi = 0; mi < 2; mi++) {
                    mma16816(acc[mi][2 * g],     ah[mi], bl[0], bl[2]);
                    mma16816(acc[mi][2 * g + 1], ah[mi], bl[1], bl[3]);
                }
            }
        }
        __syncthreads();                 // all warps done reading stage k&1
        if (k + 2 < nk) LOADS(k + 2, k & 1);
    }

    // ---------- epilogue ----------
    const int er = lane >> 2, ec = (lane & 3) * 2;
#pragma unroll
    for (int mi = 0; mi < 2; mi++) {
        const int rbase = m0 + warp_m + mi * 16 + er;
#pragma unroll
        for (int nj = 0; nj < 8; nj++) {
            const int col = n0 + warp_n + nj * 8 + ec;
            const float b0 = bias[col], b1 = bias[col + 1];
            float2 v;
            v.x = acc[mi][nj][0] + b0;
            v.y = acc[mi][nj][1] + b1;
            *(float2*)&C[(size_t)rbase * Ntot + col] = v;
            v.x = acc[mi][nj][2] + b0;
            v.y = acc[mi][nj][3] + b1;
            *(float2*)&C[(size_t)(rbase + 8) * Ntot + col] = v;
        }
    }
#undef LOADS
}

// -------------------- cell / epilogue kernels -------------------------------
__device__ __forceinline__ float sigf(float x) { return 1.0f / (1.0f + expf(-x)); }

__device__ __forceinline__ void store_h(size_t ob, float hn) {
    const __nv_bfloat16 hi = __float2bfloat16(hn);
    g_hh[ob] = hi;
    g_hl[ob] = __float2bfloat16(hn - __bfloat162float(hi));
}

__global__ void cell_leaf_kernel(const float* __restrict__ buf)
{
    const size_t idx = (size_t)blockIdx.x * blockDim.x + threadIdx.x;
    if (idx >= (size_t)B_ * LVS * H_) return;
    const int n = (int)(idx & (H_ - 1));
    const size_t r = idx >> 9;
    const float* row = buf + r * TH;
    const float i_ = row[n], o_ = row[n + 512], u_ = row[n + 1024];
    const float cn = sigf(i_) * tanhf(u_);
    const float hn = sigf(o_) * tanhf(cn);
    const int b = (int)(r >> 8), leaf = (int)(r & 255);
    const size_t ob = ((size_t)b * NN + leaf) * H_ + n;
    g_c[ob] = cn;
    store_h(ob, hn);
}

__global__ void cell_level_kernel(const float* __restrict__ buf,
                                  int lm, int off, int off_prev, int total)
{
    const int idx = blockIdx.x * blockDim.x + threadIdx.x;
    if (idx >= total) return;
    const int n = idx & (H_ - 1);
    const int r = idx >> 9;
    const int b = r >> lm;
    const int j = r & ((1 << lm) - 1);
    const float* row = buf + (size_t)r * NC;
    const float i_ = row[n], o_ = row[n + 512], u_ = row[n + 1024];
    const float f0 = row[1536 + n], f1 = row[2048 + n];
    const size_t cb = ((size_t)b * NN + off_prev + 2 * j) * H_ + n;
    const float cf = sigf(f0) * g_c[cb] + sigf(f1) * g_c[cb + H_];
    const float cn = sigf(i_) * tanhf(u_) + cf;
    const float hn = sigf(o_) * tanhf(cn);
    const size_t ob = ((size_t)b * NN + off + j) * H_ + n;
    g_c[ob] = cn;
    store_h(ob, hn);
}

__global__ void classify_kernel(const float* __restrict__ lw,
                                const float* __restrict__ lb,
                                float* __restrict__ out)
{
    const int node = blockIdx.x * blockDim.x + threadIdx.x;
    if (node >= B_ * NN) return;
    const __nv_bfloat162* hh = (const __nv_bfloat162*)(g_hh + (size_t)node * H_);
    const __nv_bfloat162* hl = (const __nv_bfloat162*)(g_hl + (size_t)node * H_);
    float acc[5] = {0.f, 0.f, 0.f, 0.f, 0.f};
#pragma unroll 4
    for (int k2 = 0; k2 < 256; k2++) {
        const float2 a = __bfloat1622float2(hh[k2]);
        const float2 b = __bfloat1622float2(hl[k2]);
        const float h0 = a.x + b.x, h1 = a.y + b.y;
#pragma unroll
        for (int c = 0; c < 5; c++)
            acc[c] += h0 * lw[c * H_ + 2 * k2] + h1 * lw[c * H_ + 2 * k2 + 1];
    }
#pragma unroll
    for (int c = 0; c < 5; c++)
        out[(size_t)node * 5 + c] = acc[c] + lb[c];
}

// -------------------- packing / gather --------------------------------------
__device__ __forceinline__ void split_bf16(float v, __nv_bfloat16* hi,
                                           __nv_bfloat16* lo, size_t i) {
    const __nv_bfloat16 h = __float2bfloat16(v);
    hi[i] = h;
    lo[i] = __float2bfloat16(v - __bfloat162float(h));
}

__global__ void pack_wcat_kernel(const float* __restrict__ Uiou,
                                 const float* __restrict__ Uf)
{
    const int idx = blockIdx.x * blockDim.x + threadIdx.x;
    if (idx >= NC * 1024) return;
    const int n = idx >> 10, k = idx & 1023;
    const float v = (n < TH) ? Uiou[(size_t)n * 1024 + k]
                             : Uf[(size_t)(n - TH) * 1024 + k];
    split_bf16(v, g_wch, g_wcl, idx);
}

__global__ void pack_wleaf_kernel(const float* __restrict__ W)
{
    const int idx = blockIdx.x * blockDim.x + threadIdx.x;
    if (idx >= TH * KLF) return;
    const int n = idx / KLF, k = idx - n * KLF;
    const float v = (k < X_) ? W[(size_t)n * X_ + k] : 0.0f;
    split_bf16(v, g_wlh, g_wll, idx);
}

__global__ void pack_bias_kernel(const float* __restrict__ bi,
                                 const float* __restrict__ bf)
{
    const int n = blockIdx.x * blockDim.x + threadIdx.x;
    if (n < NC) g_bc[n] = (n < TH) ? bi[n] : bf[n - TH];
}

__global__ void gather_x_kernel(const int* __restrict__ wid,
                                const float* __restrict__ emb)
{
    const int r = blockIdx.x;
    const int c = threadIdx.x;
    if (c >= KLF) return;
    const float v = (c < X_) ? emb[(size_t)wid[r] * X_ + c] : 0.0f;
    split_bf16(v, g_xh, g_xl, (size_t)r * KLF + c);
}

// -------------------- launch ------------------------------------------------
extern "C" void kernel_launch(void* const* d_in, const int* in_sizes, int n_in,
                              void* d_out, int out_size)
{
    const int*   wordid  = (const int*)  d_in[0];
    const float* emb     = (const float*)d_in[1];
    const float* W_iou_w = (const float*)d_in[2];
    const float* W_iou_b = (const float*)d_in[3];
    const float* U_iou_w = (const float*)d_in[4];
    const float* U_iou_b = (const float*)d_in[5];
    const float* U_f_w   = (const float*)d_in[6];
    const float* U_f_b   = (const float*)d_in[7];
    const float* lin_w   = (const float*)d_in[8];
    const float* lin_b   = (const float*)d_in[9];
    float* out = (float*)d_out;
    (void)in_sizes; (void)n_in; (void)out_size;

    float *pbuf, *pbc;
    __nv_bfloat16 *phh, *phl, *pxh, *pxl, *pwch, *pwcl, *pwlh, *pwll;
    cudaGetSymbolAddress((void**)&pbuf, g_buf);
    cudaGetSymbolAddress((void**)&pbc,  g_bc);
    cudaGetSymbolAddress((void**)&phh,  g_hh);
    cudaGetSymbolAddress((void**)&phl,  g_hl);
    cudaGetSymbolAddress((void**)&pxh,  g_xh);
    cudaGetSymbolAddress((void**)&pxl,  g_xl);
    cudaGetSymbolAddress((void**)&pwch, g_wch);
    cudaGetSymbolAddress((void**)&pwcl, g_wcl);
    cudaGetSymbolAddress((void**)&pwlh, g_wlh);
    cudaGetSymbolAddress((void**)&pwll, g_wll);

    cudaFuncSetAttribute(gemm_mma_kernel,
                         cudaFuncAttributeMaxDynamicSharedMemorySize, SMEM_BYTES);

    // ---- prep ----
    pack_wcat_kernel <<<(NC * 1024 + 255) / 256, 256>>>(U_iou_w, U_f_w);
    pack_wleaf_kernel<<<(TH * KLF + 255) / 256, 256>>>(W_iou_w);
    pack_bias_kernel <<<(NC + 255) / 256, 256>>>(U_iou_b, U_f_b);
    gather_x_kernel  <<<B_ * LVS, KLF>>>(wordid, emb);

    // ---- leaves ----
    {
        dim3 g(TH / BN, (B_ * LVS) / BM);
        gemm_mma_kernel<<<g, 256, SMEM_BYTES>>>(pxh, pxl, pwlh, pwll, W_iou_b,
                                                pbuf, TH, KLF, KLF / BK, -1, 0);
        cell_leaf_kernel<<<(B_ * LVS * H_) / 256, 256>>>(pbuf);
    }

    // ---- internal levels ----
    static const int offs[10] = {0, 256, 384, 448, 480, 496, 504, 508, 510, 511};
    for (int l = 1; l <= 8; l++) {
        const int m = LVS >> l;
        const int M = B_ * m;
        const int lm = 8 - l;
        dim3 g(NC / BN, M / BM);
        gemm_mma_kernel<<<g, 256, SMEM_BYTES>>>(phh, phl, pwch, pwcl, pbc,
                                                pbuf, NC, 1024, 1024 / BK,
                                                lm, offs[l - 1]);
        const int total = M * H_;
        cell_level_kernel<<<(total + 255) / 256, 256>>>(pbuf, lm, offs[l],
                                                        offs[l - 1], total);
    }

    // ---- classifier ----
    classify_kernel<<<(B_ * NN + 127) / 128, 128>>>(lin_w, lin_b, out);
}